// round 3
// baseline (speedup 1.0000x reference)
#include <cuda_runtime.h>
#include <cstdint>

// WindowSlice: out[b, t, c] = lerp(x[b, starts[b]+lo(t), c], x[b, starts[b]+lo(t)+1, c], w(t))
// B=64, T=4096, C=128, L = ceil(0.9*T) = 3687.
// HBM-bound. Strategy: MLP=8 per thread (4 t-rows, 8 independent float4 loads),
// streaming stores so the x read-stream keeps L2 residency across graph replays.

#define B_DIM 64
#define T_DIM 4096
#define C_DIM 128
#define L_DIM 3687            // ceil(0.9 * 4096)
#define C4 (C_DIM / 4)        // 32 float4 per row
#define ROWS 4                // t-rows per thread

__device__ __forceinline__ void interp_params(unsigned t, int& lo, float& w)
{
    float step = (float)L_DIM / (float)(T_DIM - 1);
    float q = (float)t * step;
    float tc = fminf(q, (float)(L_DIM - 1));
    float lof = floorf(tc);
    lof = fminf(lof, (float)(L_DIM - 2));
    lo = (int)lof;
    w = tc - lof;
}

__global__ __launch_bounds__(256) void window_slice_kernel(
    const float* __restrict__ x,
    const int* __restrict__ starts,
    float* __restrict__ out)
{
    // Each thread: 4 adjacent t rows at the same c4.
    // idx layout: [b (64)] [tg (1024)] [c4 (32)], t_i = 4*tg + i.
    unsigned idx = blockIdx.x * 256u + threadIdx.x;
    unsigned c4 = idx & (C4 - 1);                   // lane 0..31
    unsigned tg = (idx >> 5) & (T_DIM / ROWS - 1);  // 0..1023
    unsigned b  = idx >> 15;                        // 0..63
    unsigned t0 = tg * ROWS;

    int s = __ldg(&starts[b]);
    long long brow = (long long)b * T_DIM;

    int lo[ROWS];
    float w[ROWS];
#pragma unroll
    for (int i = 0; i < ROWS; i++)
        interp_params(t0 + i, lo[i], w[i]);

    // 8 independent loads, front-batched -> MLP 8
    float4 vlo[ROWS], vhi[ROWS];
#pragma unroll
    for (int i = 0; i < ROWS; i++) {
        long long base = (brow + (s + lo[i])) * C_DIM + c4 * 4;
        vlo[i] = __ldg((const float4*)(x + base));
        vhi[i] = __ldg((const float4*)(x + base + C_DIM));
    }

#pragma unroll
    for (int i = 0; i < ROWS; i++) {
        float4 r;
        r.x = fmaf(w[i], vhi[i].x - vlo[i].x, vlo[i].x);
        r.y = fmaf(w[i], vhi[i].y - vlo[i].y, vlo[i].y);
        r.z = fmaf(w[i], vhi[i].z - vlo[i].z, vlo[i].z);
        r.w = fmaf(w[i], vhi[i].w - vlo[i].w, vlo[i].w);
        float4* o = (float4*)out + ((size_t)(b * T_DIM + t0 + i) * C4 + c4);
        __stcs(o, r);
    }
}

extern "C" void kernel_launch(void* const* d_in, const int* in_sizes, int n_in,
                              void* d_out, int out_size)
{
    const float* x = (const float*)d_in[0];
    const int* starts = (const int*)d_in[1];
    float* out = (float*)d_out;

    // threads = B * (T/ROWS) * C4 = 64 * 1024 * 32 = 2,097,152 -> 8192 blocks x 256
    const unsigned total = B_DIM * (T_DIM / ROWS) * C4;
    window_slice_kernel<<<total / 256, 256>>>(x, starts, out);
}

// round 5
// speedup vs baseline: 1.0051x; 1.0051x over previous
#include <cuda_runtime.h>
#include <cstdint>

// WindowSlice: out[b, t, c] = lerp(x[b, starts[b]+lo(t), c], x[b, starts[b]+lo(t)+1, c], w(t))
// B=64, T=4096, C=128, L = ceil(0.9*T) = 3687.
// HBM-bound. Software-pipelined grid-stride (depth 2): each thread handles a fixed
// (tt, c4) across 8 batches; next iteration's 4 float4 loads issue before the
// current iteration's compute/store -> sustained MLP ~8 with bounded registers.

#define B_DIM 64
#define T_DIM 4096
#define C_DIM 128
#define L_DIM 3687            // ceil(0.9 * 4096)
#define C4 (C_DIM / 4)        // 32 float4 per row
#define GRID 2048
#define ITERS 8               // (B*T/2*C4) / (GRID*256) = 16384/2048

__device__ __forceinline__ void interp_params(unsigned t, int& lo, float& w)
{
    float step = (float)L_DIM / (float)(T_DIM - 1);
    float q = (float)t * step;
    float tc = fminf(q, (float)(L_DIM - 1));
    float lof = floorf(tc);
    lof = fminf(lof, (float)(L_DIM - 2));
    lo = (int)lof;
    w = tc - lof;
}

__device__ __forceinline__ float4 lerp4(float4 a, float4 b, float w)
{
    float4 r;
    r.x = fmaf(w, b.x - a.x, a.x);
    r.y = fmaf(w, b.y - a.y, a.y);
    r.z = fmaf(w, b.z - a.z, a.z);
    r.w = fmaf(w, b.w - a.w, a.w);
    return r;
}

__global__ __launch_bounds__(256) void window_slice_kernel(
    const float* __restrict__ x,
    const int* __restrict__ starts,
    float* __restrict__ out)
{
    // Item index j0 decomposes as [b0 (0..7)] [tt (0..2047)] [c4 (0..31)].
    // Grid-stride adds 2048*256 = 2^19 -> b += 8 per iteration; tt, c4 fixed.
    unsigned j0 = blockIdx.x * 256u + threadIdx.x;
    unsigned c4 = j0 & (C4 - 1);
    unsigned tt = (j0 >> 5) & (T_DIM / 2 - 1);
    unsigned b0 = j0 >> 16;                 // 0..7
    unsigned t0 = tt * 2, t1 = t0 + 1;

    // Interp params invariant across the loop (depend on t only).
    int lo0, lo1;
    float w0, w1;
    interp_params(t0, lo0, w0);
    interp_params(t1, lo1, w1);

    const unsigned col = c4 * 4;
    float4* out4 = (float4*)out;

    // Prologue: loads for iteration 0.
    int s = __ldg(&starts[b0]);
    {
    }
    long long base0 = ((long long)(b0 * T_DIM) + s + lo0) * C_DIM + col;
    long long base1 = ((long long)(b0 * T_DIM) + s + lo1) * C_DIM + col;
    float4 a0 = __ldg((const float4*)(x + base0));
    float4 a1 = __ldg((const float4*)(x + base0 + C_DIM));
    float4 a2 = __ldg((const float4*)(x + base1));
    float4 a3 = __ldg((const float4*)(x + base1 + C_DIM));

#pragma unroll 1
    for (int i = 0; i < ITERS; i++) {
        unsigned b = b0 + (unsigned)i * 8u;

        // Issue next iteration's loads BEFORE consuming current values.
        float4 n0, n1, n2, n3;
        if (i + 1 < ITERS) {
            unsigned bn = b + 8u;
            int sn = __ldg(&starts[bn]);
            long long nb0 = ((long long)(bn * T_DIM) + sn + lo0) * C_DIM + col;
            long long nb1 = ((long long)(bn * T_DIM) + sn + lo1) * C_DIM + col;
            n0 = __ldg((const float4*)(x + nb0));
            n1 = __ldg((const float4*)(x + nb0 + C_DIM));
            n2 = __ldg((const float4*)(x + nb1));
            n3 = __ldg((const float4*)(x + nb1 + C_DIM));
        }

        // Compute + streaming-store current.
        float4 r0 = lerp4(a0, a1, w0);
        float4 r1 = lerp4(a2, a3, w1);
        __stcs(out4 + ((size_t)(b * T_DIM + t0) * C4 + c4), r0);
        __stcs(out4 + ((size_t)(b * T_DIM + t1) * C4 + c4), r1);

        a0 = n0; a1 = n1; a2 = n2; a3 = n3;
    }
}

extern "C" void kernel_launch(void* const* d_in, const int* in_sizes, int n_in,
                              void* d_out, int out_size)
{
    const float* x = (const float*)d_in[0];
    const int* starts = (const int*)d_in[1];
    float* out = (float*)d_out;

    window_slice_kernel<<<GRID, 256>>>(x, starts, out);
}

// round 6
// speedup vs baseline: 1.0148x; 1.0097x over previous
#include <cuda_runtime.h>
#include <cstdint>

// WindowSlice: out[b, t, c] = lerp(x[b, starts[b]+lo(t), c], x[b, starts[b]+lo(t)+1, c], w(t))
// B=64, T=4096, C=128, L = ceil(0.9*T) = 3687.
// HBM-bound at the traffic floor. R2 structure (2 t-rows/thread, MLP 4) +
// WRITE-THROUGH stores: out stream bypasses L2 retention so the x working set
// (~115 MB, just under the 126 MB L2) stays resident across graph replays,
// cutting DRAM read misses.

#define B_DIM 64
#define T_DIM 4096
#define C_DIM 128
#define L_DIM 3687            // ceil(0.9 * 4096)
#define C4 (C_DIM / 4)        // 32 float4 per row

__device__ __forceinline__ void interp_params(unsigned t, int& lo, float& w)
{
    float step = (float)L_DIM / (float)(T_DIM - 1);
    float q = (float)t * step;
    float tc = fminf(q, (float)(L_DIM - 1));
    float lof = floorf(tc);
    lof = fminf(lof, (float)(L_DIM - 2));
    lo = (int)lof;
    w = tc - lof;
}

__global__ __launch_bounds__(256) void window_slice_kernel(
    const float* __restrict__ x,
    const int* __restrict__ starts,
    float* __restrict__ out)
{
    // Each thread handles TWO adjacent t rows at the same c4.
    // idx layout: [b (64)] [tt (2048)] [c4 (32)], t0 = 2*tt, t1 = 2*tt+1.
    unsigned idx = blockIdx.x * 256u + threadIdx.x;
    unsigned c4 = idx & (C4 - 1);             // 0..31 (lane)
    unsigned tt = (idx >> 5) & (T_DIM/2 - 1); // 0..2047
    unsigned b  = idx >> 16;                  // 0..63
    unsigned t0 = tt * 2;
    unsigned t1 = t0 + 1;

    int lo0, lo1;
    float w0, w1;
    interp_params(t0, lo0, w0);
    interp_params(t1, lo1, w1);

    int s = __ldg(&starts[b]);
    long long brow = (long long)b * T_DIM;
    long long base0 = (brow + (s + lo0)) * C_DIM + c4 * 4;
    long long base1 = (brow + (s + lo1)) * C_DIM + c4 * 4;

    // 4 independent loads -> MLP 4
    float4 vlo0 = __ldg((const float4*)(x + base0));
    float4 vhi0 = __ldg((const float4*)(x + base0 + C_DIM));
    float4 vlo1 = __ldg((const float4*)(x + base1));
    float4 vhi1 = __ldg((const float4*)(x + base1 + C_DIM));

    float4 r0, r1;
    r0.x = fmaf(w0, vhi0.x - vlo0.x, vlo0.x);
    r0.y = fmaf(w0, vhi0.y - vlo0.y, vlo0.y);
    r0.z = fmaf(w0, vhi0.z - vlo0.z, vlo0.z);
    r0.w = fmaf(w0, vhi0.w - vlo0.w, vlo0.w);
    r1.x = fmaf(w1, vhi1.x - vlo1.x, vlo1.x);
    r1.y = fmaf(w1, vhi1.y - vlo1.y, vlo1.y);
    r1.z = fmaf(w1, vhi1.z - vlo1.z, vlo1.z);
    r1.w = fmaf(w1, vhi1.w - vlo1.w, vlo1.w);

    // Write-through stores: don't retain out lines in L2 -> x stays resident.
    float4* o0 = (float4*)out + ((size_t)(b * T_DIM + t0) * C4 + c4);
    float4* o1 = (float4*)out + ((size_t)(b * T_DIM + t1) * C4 + c4);
    __stwt(o0, r0);
    __stwt(o1, r1);
}

extern "C" void kernel_launch(void* const* d_in, const int* in_sizes, int n_in,
                              void* d_out, int out_size)
{
    const float* x = (const float*)d_in[0];
    const int* starts = (const int*)d_in[1];
    float* out = (float*)d_out;

    // threads = B * (T/2) * C4 = 64 * 2048 * 32 = 4,194,304 -> 16384 blocks x 256
    const unsigned total = B_DIM * (T_DIM / 2) * C4;
    window_slice_kernel<<<total / 256, 256>>>(x, starts, out);
}

// round 7
// speedup vs baseline: 1.0156x; 1.0007x over previous
#include <cuda_runtime.h>
#include <cstdint>

// WindowSlice: out[b, t, c] = lerp(x[b, starts[b]+lo(t), c], x[b, starts[b]+lo(t)+1, c], w(t))
// B=64, T=4096, C=128, L = ceil(0.9*T) = 3687.
// HBM-bound; DRAM traffic = 128 MB compulsory writes + ~71 MB x read misses.
// The x read set (~121 MB) fits in the 126 MB L2: bias L2 replacement with
// cache-policy hints — x loads evict_last (sticky, persists across graph
// replays), out stores evict_first (streaming).

#define B_DIM 64
#define T_DIM 4096
#define C_DIM 128
#define L_DIM 3687            // ceil(0.9 * 4096)
#define C4 (C_DIM / 4)        // 32 float4 per row

__device__ __forceinline__ void interp_params(unsigned t, int& lo, float& w)
{
    float step = (float)L_DIM / (float)(T_DIM - 1);
    float q = (float)t * step;
    float tc = fminf(q, (float)(L_DIM - 1));
    float lof = floorf(tc);
    lof = fminf(lof, (float)(L_DIM - 2));
    lo = (int)lof;
    w = tc - lof;
}

__device__ __forceinline__ float4 ldg_keep(const float4* p, uint64_t pol)
{
    float4 v;
    asm("ld.global.nc.L2::cache_hint.v4.f32 {%0,%1,%2,%3}, [%4], %5;"
        : "=f"(v.x), "=f"(v.y), "=f"(v.z), "=f"(v.w)
        : "l"(p), "l"(pol));
    return v;
}

__device__ __forceinline__ void stg_stream(float4* p, float4 v, uint64_t pol)
{
    asm volatile("st.global.L2::cache_hint.v4.f32 [%0], {%1,%2,%3,%4}, %5;"
                 :: "l"(p), "f"(v.x), "f"(v.y), "f"(v.z), "f"(v.w), "l"(pol)
                 : "memory");
}

__global__ __launch_bounds__(256) void window_slice_kernel(
    const float* __restrict__ x,
    const int* __restrict__ starts,
    float* __restrict__ out)
{
    // L2 policies: keep x resident, stream out.
    uint64_t pol_keep, pol_stream;
    asm("createpolicy.fractional.L2::evict_last.b64 %0, 1.0;" : "=l"(pol_keep));
    asm("createpolicy.fractional.L2::evict_first.b64 %0, 1.0;" : "=l"(pol_stream));

    // Each thread handles TWO adjacent t rows at the same c4.
    // idx layout: [b (64)] [tt (2048)] [c4 (32)], t0 = 2*tt, t1 = 2*tt+1.
    unsigned idx = blockIdx.x * 256u + threadIdx.x;
    unsigned c4 = idx & (C4 - 1);             // 0..31 (lane)
    unsigned tt = (idx >> 5) & (T_DIM/2 - 1); // 0..2047
    unsigned b  = idx >> 16;                  // 0..63
    unsigned t0 = tt * 2;
    unsigned t1 = t0 + 1;

    int lo0, lo1;
    float w0, w1;
    interp_params(t0, lo0, w0);
    interp_params(t1, lo1, w1);

    int s = __ldg(&starts[b]);
    long long brow = (long long)b * T_DIM;
    long long base0 = (brow + (s + lo0)) * C_DIM + c4 * 4;
    long long base1 = (brow + (s + lo1)) * C_DIM + c4 * 4;

    // 4 independent loads (MLP 4), all marked L2-sticky.
    float4 vlo0 = ldg_keep((const float4*)(x + base0), pol_keep);
    float4 vhi0 = ldg_keep((const float4*)(x + base0 + C_DIM), pol_keep);
    float4 vlo1 = ldg_keep((const float4*)(x + base1), pol_keep);
    float4 vhi1 = ldg_keep((const float4*)(x + base1 + C_DIM), pol_keep);

    float4 r0, r1;
    r0.x = fmaf(w0, vhi0.x - vlo0.x, vlo0.x);
    r0.y = fmaf(w0, vhi0.y - vlo0.y, vlo0.y);
    r0.z = fmaf(w0, vhi0.z - vlo0.z, vlo0.z);
    r0.w = fmaf(w0, vhi0.w - vlo0.w, vlo0.w);
    r1.x = fmaf(w1, vhi1.x - vlo1.x, vlo1.x);
    r1.y = fmaf(w1, vhi1.y - vlo1.y, vlo1.y);
    r1.z = fmaf(w1, vhi1.z - vlo1.z, vlo1.z);
    r1.w = fmaf(w1, vhi1.w - vlo1.w, vlo1.w);

    // Streaming stores (evict_first): don't displace x.
    float4* o0 = (float4*)out + ((size_t)(b * T_DIM + t0) * C4 + c4);
    float4* o1 = (float4*)out + ((size_t)(b * T_DIM + t1) * C4 + c4);
    stg_stream(o0, r0, pol_stream);
    stg_stream(o1, r1, pol_stream);
}

extern "C" void kernel_launch(void* const* d_in, const int* in_sizes, int n_in,
                              void* d_out, int out_size)
{
    const float* x = (const float*)d_in[0];
    const int* starts = (const int*)d_in[1];
    float* out = (float*)d_out;

    // threads = B * (T/2) * C4 = 64 * 2048 * 32 = 4,194,304 -> 16384 blocks x 256
    const unsigned total = B_DIM * (T_DIM / 2) * C4;
    window_slice_kernel<<<total / 256, 256>>>(x, starts, out);
}

// round 8
// speedup vs baseline: 1.0164x; 1.0007x over previous
#include <cuda_runtime.h>
#include <cstdint>

// WindowSlice: out[b, t, c] = lerp(x[b, starts[b]+lo(t), c], x[b, starts[b]+lo(t)+1, c], w(t))
// B=64, T=4096, C=128, L = ceil(0.9*T) = 3687.
// HBM-bound at the practical traffic floor (~199 MB: 128 MB compulsory writes
// + ~70 MB x read misses; verified invariant across MLP/pipeline/L2-policy
// variants). Best structure: 2 t-rows per thread (MLP 4), write-through
// stores. This round: block=512 to cut wave-transition overhead.

#define B_DIM 64
#define T_DIM 4096
#define C_DIM 128
#define L_DIM 3687            // ceil(0.9 * 4096)
#define C4 (C_DIM / 4)        // 32 float4 per row
#define TPB 512

__device__ __forceinline__ void interp_params(unsigned t, int& lo, float& w)
{
    float step = (float)L_DIM / (float)(T_DIM - 1);
    float q = (float)t * step;
    float tc = fminf(q, (float)(L_DIM - 1));
    float lof = floorf(tc);
    lof = fminf(lof, (float)(L_DIM - 2));
    lo = (int)lof;
    w = tc - lof;
}

__global__ __launch_bounds__(TPB) void window_slice_kernel(
    const float* __restrict__ x,
    const int* __restrict__ starts,
    float* __restrict__ out)
{
    // Each thread handles TWO adjacent t rows at the same c4.
    // idx layout: [b (64)] [tt (2048)] [c4 (32)], t0 = 2*tt, t1 = 2*tt+1.
    unsigned idx = blockIdx.x * (unsigned)TPB + threadIdx.x;
    unsigned c4 = idx & (C4 - 1);             // 0..31 (lane)
    unsigned tt = (idx >> 5) & (T_DIM/2 - 1); // 0..2047
    unsigned b  = idx >> 16;                  // 0..63
    unsigned t0 = tt * 2;
    unsigned t1 = t0 + 1;

    int lo0, lo1;
    float w0, w1;
    interp_params(t0, lo0, w0);
    interp_params(t1, lo1, w1);

    int s = __ldg(&starts[b]);
    long long brow = (long long)b * T_DIM;
    long long base0 = (brow + (s + lo0)) * C_DIM + c4 * 4;
    long long base1 = (brow + (s + lo1)) * C_DIM + c4 * 4;

    // 4 independent loads -> MLP 4
    float4 vlo0 = __ldg((const float4*)(x + base0));
    float4 vhi0 = __ldg((const float4*)(x + base0 + C_DIM));
    float4 vlo1 = __ldg((const float4*)(x + base1));
    float4 vhi1 = __ldg((const float4*)(x + base1 + C_DIM));

    float4 r0, r1;
    r0.x = fmaf(w0, vhi0.x - vlo0.x, vlo0.x);
    r0.y = fmaf(w0, vhi0.y - vlo0.y, vlo0.y);
    r0.z = fmaf(w0, vhi0.z - vlo0.z, vlo0.z);
    r0.w = fmaf(w0, vhi0.w - vlo0.w, vlo0.w);
    r1.x = fmaf(w1, vhi1.x - vlo1.x, vlo1.x);
    r1.y = fmaf(w1, vhi1.y - vlo1.y, vlo1.y);
    r1.z = fmaf(w1, vhi1.z - vlo1.z, vlo1.z);
    r1.w = fmaf(w1, vhi1.w - vlo1.w, vlo1.w);

    // Write-through stores: best-measured variant (R6).
    float4* o0 = (float4*)out + ((size_t)(b * T_DIM + t0) * C4 + c4);
    float4* o1 = (float4*)out + ((size_t)(b * T_DIM + t1) * C4 + c4);
    __stwt(o0, r0);
    __stwt(o1, r1);
}

extern "C" void kernel_launch(void* const* d_in, const int* in_sizes, int n_in,
                              void* d_out, int out_size)
{
    const float* x = (const float*)d_in[0];
    const int* starts = (const int*)d_in[1];
    float* out = (float*)d_out;

    // threads = B * (T/2) * C4 = 64 * 2048 * 32 = 4,194,304 -> 8192 blocks x 512
    const unsigned total = B_DIM * (T_DIM / 2) * C4;
    window_slice_kernel<<<total / TPB, TPB>>>(x, starts, out);
}

// round 9
// speedup vs baseline: 1.0556x; 1.0386x over previous
#include <cuda_runtime.h>
#include <cstdint>

// WindowSlice: out[b, t, c] = lerp(x[b, starts[b]+lo(t), c], x[b, starts[b]+lo(t)+1, c], w(t))
// B=64, T=4096, C=128, L = ceil(0.9*T) = 3687.
// HBM-bound at the practical traffic floor (~200 MB = 128 MB compulsory writes
// + ~70 MB x read misses; invariant across MLP / pipeline / L2-policy / store-op
// variants). Winning structure: 2 t-rows per thread (MLP 4), write-through
// stores. This round: block=1024 to halve wave-transition overhead.

#define B_DIM 64
#define T_DIM 4096
#define C_DIM 128
#define L_DIM 3687            // ceil(0.9 * 4096)
#define C4 (C_DIM / 4)        // 32 float4 per row
#define TPB 1024

__device__ __forceinline__ void interp_params(unsigned t, int& lo, float& w)
{
    float step = (float)L_DIM / (float)(T_DIM - 1);
    float q = (float)t * step;
    float tc = fminf(q, (float)(L_DIM - 1));
    float lof = floorf(tc);
    lof = fminf(lof, (float)(L_DIM - 2));
    lo = (int)lof;
    w = tc - lof;
}

__global__ __launch_bounds__(TPB) void window_slice_kernel(
    const float* __restrict__ x,
    const int* __restrict__ starts,
    float* __restrict__ out)
{
    // Each thread handles TWO adjacent t rows at the same c4.
    // idx layout: [b (64)] [tt (2048)] [c4 (32)], t0 = 2*tt, t1 = 2*tt+1.
    unsigned idx = blockIdx.x * (unsigned)TPB + threadIdx.x;
    unsigned c4 = idx & (C4 - 1);             // 0..31 (lane)
    unsigned tt = (idx >> 5) & (T_DIM/2 - 1); // 0..2047
    unsigned b  = idx >> 16;                  // 0..63
    unsigned t0 = tt * 2;
    unsigned t1 = t0 + 1;

    int lo0, lo1;
    float w0, w1;
    interp_params(t0, lo0, w0);
    interp_params(t1, lo1, w1);

    int s = __ldg(&starts[b]);
    long long brow = (long long)b * T_DIM;
    long long base0 = (brow + (s + lo0)) * C_DIM + c4 * 4;
    long long base1 = (brow + (s + lo1)) * C_DIM + c4 * 4;

    // 4 independent loads -> MLP 4
    float4 vlo0 = __ldg((const float4*)(x + base0));
    float4 vhi0 = __ldg((const float4*)(x + base0 + C_DIM));
    float4 vlo1 = __ldg((const float4*)(x + base1));
    float4 vhi1 = __ldg((const float4*)(x + base1 + C_DIM));

    float4 r0, r1;
    r0.x = fmaf(w0, vhi0.x - vlo0.x, vlo0.x);
    r0.y = fmaf(w0, vhi0.y - vlo0.y, vlo0.y);
    r0.z = fmaf(w0, vhi0.z - vlo0.z, vlo0.z);
    r0.w = fmaf(w0, vhi0.w - vlo0.w, vlo0.w);
    r1.x = fmaf(w1, vhi1.x - vlo1.x, vlo1.x);
    r1.y = fmaf(w1, vhi1.y - vlo1.y, vlo1.y);
    r1.z = fmaf(w1, vhi1.z - vlo1.z, vlo1.z);
    r1.w = fmaf(w1, vhi1.w - vlo1.w, vlo1.w);

    // Write-through stores (best-measured).
    float4* o0 = (float4*)out + ((size_t)(b * T_DIM + t0) * C4 + c4);
    float4* o1 = (float4*)out + ((size_t)(b * T_DIM + t1) * C4 + c4);
    __stwt(o0, r0);
    __stwt(o1, r1);
}

extern "C" void kernel_launch(void* const* d_in, const int* in_sizes, int n_in,
                              void* d_out, int out_size)
{
    const float* x = (const float*)d_in[0];
    const int* starts = (const int*)d_in[1];
    float* out = (float*)d_out;

    // threads = B * (T/2) * C4 = 64 * 2048 * 32 = 4,194,304 -> 4096 blocks x 1024
    const unsigned total = B_DIM * (T_DIM / 2) * C4;
    window_slice_kernel<<<total / TPB, TPB>>>(x, starts, out);
}